// round 1
// baseline (speedup 1.0000x reference)
#include <cuda_runtime.h>
#include <cuda_bf16.h>
#include <math.h>

// Problem dims (fixed)
#define B_SZ   4096
#define N_IN   4096
#define N_CTX  512
#define UNITS  4096
#define RANK   256

// Tiling
#define BM 64
#define BN 64
#define BK 16
#define TM 4
#define TN 4
#define NTHREADS 256

// Scratch (device globals — no allocation allowed in kernel_launch)
__device__ float g_schi[B_SZ * RANK];  // S[r] * sigmoid(context@W + B)
__device__ float g_t[B_SZ * RANK];     // (inputs@U) * schi

// ---------------------------------------------------------------------------
// Kernel A: schi[b,r] = S[r] * sigmoid( (context @ W)[b,r] + Bvec[r] )
// A = context [M=4096, K=512] row-major, B = W [K=512, N=256] row-major
// ---------------------------------------------------------------------------
__global__ __launch_bounds__(NTHREADS)
void k_chi(const float* __restrict__ A, const float* __restrict__ Bm,
           const float* __restrict__ S, const float* __restrict__ Bvec)
{
    const int K = N_CTX, N = RANK;
    __shared__ float As[BK][BM];
    __shared__ float Bs[BK][BN];

    int tid  = threadIdx.x;
    int brow = blockIdx.y * BM;
    int bcol = blockIdx.x * BN;

    int a_row = tid >> 2;          // 0..63
    int a_col = (tid & 3) << 2;    // 0,4,8,12
    int b_row = tid >> 4;          // 0..15
    int b_col = (tid & 15) << 2;   // 0..60
    int ty = (tid >> 4) << 2;      // m offset 0..60
    int tx = (tid & 15) << 2;      // n offset 0..60

    float acc[TM][TN];
#pragma unroll
    for (int m = 0; m < TM; m++)
#pragma unroll
        for (int n = 0; n < TN; n++) acc[m][n] = 0.f;

    for (int k0 = 0; k0 < K; k0 += BK) {
        float4 av = *(const float4*)(A + (size_t)(brow + a_row) * K + k0 + a_col);
        As[a_col + 0][a_row] = av.x;
        As[a_col + 1][a_row] = av.y;
        As[a_col + 2][a_row] = av.z;
        As[a_col + 3][a_row] = av.w;
        *(float4*)(&Bs[b_row][b_col]) =
            *(const float4*)(Bm + (size_t)(k0 + b_row) * N + bcol + b_col);
        __syncthreads();
#pragma unroll
        for (int kk = 0; kk < BK; kk++) {
            float4 a4 = *(const float4*)(&As[kk][ty]);
            float4 b4 = *(const float4*)(&Bs[kk][tx]);
            float am[4] = {a4.x, a4.y, a4.z, a4.w};
            float bn[4] = {b4.x, b4.y, b4.z, b4.w};
#pragma unroll
            for (int m = 0; m < TM; m++)
#pragma unroll
                for (int n = 0; n < TN; n++)
                    acc[m][n] = fmaf(am[m], bn[n], acc[m][n]);
        }
        __syncthreads();
    }

#pragma unroll
    for (int m = 0; m < TM; m++) {
        int row = brow + ty + m;
#pragma unroll
        for (int n = 0; n < TN; n++) {
            int col = bcol + tx + n;
            float x = acc[m][n] + Bvec[col];
            float sg = 1.f / (1.f + expf(-x));
            g_schi[(size_t)row * RANK + col] = S[col] * sg;
        }
    }
}

// ---------------------------------------------------------------------------
// Kernel B: t[b,r] = (inputs @ U)[b,r] * schi[b,r]
// A = inputs [M=4096, K=4096], B = U [K=4096, N=256] both row-major
// ---------------------------------------------------------------------------
__global__ __launch_bounds__(NTHREADS)
void k_t(const float* __restrict__ A, const float* __restrict__ Bm)
{
    const int K = N_IN, N = RANK;
    __shared__ float As[BK][BM];
    __shared__ float Bs[BK][BN];

    int tid  = threadIdx.x;
    int brow = blockIdx.y * BM;
    int bcol = blockIdx.x * BN;

    int a_row = tid >> 2;
    int a_col = (tid & 3) << 2;
    int b_row = tid >> 4;
    int b_col = (tid & 15) << 2;
    int ty = (tid >> 4) << 2;
    int tx = (tid & 15) << 2;

    float acc[TM][TN];
#pragma unroll
    for (int m = 0; m < TM; m++)
#pragma unroll
        for (int n = 0; n < TN; n++) acc[m][n] = 0.f;

    for (int k0 = 0; k0 < K; k0 += BK) {
        float4 av = *(const float4*)(A + (size_t)(brow + a_row) * K + k0 + a_col);
        As[a_col + 0][a_row] = av.x;
        As[a_col + 1][a_row] = av.y;
        As[a_col + 2][a_row] = av.z;
        As[a_col + 3][a_row] = av.w;
        *(float4*)(&Bs[b_row][b_col]) =
            *(const float4*)(Bm + (size_t)(k0 + b_row) * N + bcol + b_col);
        __syncthreads();
#pragma unroll
        for (int kk = 0; kk < BK; kk++) {
            float4 a4 = *(const float4*)(&As[kk][ty]);
            float4 b4 = *(const float4*)(&Bs[kk][tx]);
            float am[4] = {a4.x, a4.y, a4.z, a4.w};
            float bn[4] = {b4.x, b4.y, b4.z, b4.w};
#pragma unroll
            for (int m = 0; m < TM; m++)
#pragma unroll
                for (int n = 0; n < TN; n++)
                    acc[m][n] = fmaf(am[m], bn[n], acc[m][n]);
        }
        __syncthreads();
    }

#pragma unroll
    for (int m = 0; m < TM; m++) {
        int row = brow + ty + m;
#pragma unroll
        for (int n = 0; n < TN; n++) {
            int col = bcol + tx + n;
            size_t idx = (size_t)row * RANK + col;
            g_t[idx] = acc[m][n] * g_schi[idx];
        }
    }
}

// ---------------------------------------------------------------------------
// Kernel C: out[b,m] = relu( (t @ V^T)[b,m] + 2*bias[m] )
// A = t [M=4096, K=256] row-major, B = V [N=4096, K=256] row-major (N-major)
// ---------------------------------------------------------------------------
__global__ __launch_bounds__(NTHREADS)
void k_out(float* __restrict__ out, const float* __restrict__ Vm,
           const float* __restrict__ bias)
{
    const int K = RANK, N = UNITS;
    __shared__ float As[BK][BM];
    __shared__ float Bs[BK][BN];

    int tid  = threadIdx.x;
    int brow = blockIdx.y * BM;
    int bcol = blockIdx.x * BN;

    int a_row = tid >> 2;          // 0..63 (m within tile)
    int a_col = (tid & 3) << 2;    // k
    int v_row = tid >> 2;          // 0..63 (n within tile)
    int v_col = (tid & 3) << 2;    // k
    int ty = (tid >> 4) << 2;
    int tx = (tid & 15) << 2;

    float acc[TM][TN];
#pragma unroll
    for (int m = 0; m < TM; m++)
#pragma unroll
        for (int n = 0; n < TN; n++) acc[m][n] = 0.f;

    for (int k0 = 0; k0 < K; k0 += BK) {
        float4 av = *(const float4*)(g_t + (size_t)(brow + a_row) * K + k0 + a_col);
        As[a_col + 0][a_row] = av.x;
        As[a_col + 1][a_row] = av.y;
        As[a_col + 2][a_row] = av.z;
        As[a_col + 3][a_row] = av.w;
        float4 bv = *(const float4*)(Vm + (size_t)(bcol + v_row) * K + k0 + v_col);
        Bs[v_col + 0][v_row] = bv.x;
        Bs[v_col + 1][v_row] = bv.y;
        Bs[v_col + 2][v_row] = bv.z;
        Bs[v_col + 3][v_row] = bv.w;
        __syncthreads();
#pragma unroll
        for (int kk = 0; kk < BK; kk++) {
            float4 a4 = *(const float4*)(&As[kk][ty]);
            float4 b4 = *(const float4*)(&Bs[kk][tx]);
            float am[4] = {a4.x, a4.y, a4.z, a4.w};
            float bn[4] = {b4.x, b4.y, b4.z, b4.w};
#pragma unroll
            for (int m = 0; m < TM; m++)
#pragma unroll
                for (int n = 0; n < TN; n++)
                    acc[m][n] = fmaf(am[m], bn[n], acc[m][n]);
        }
        __syncthreads();
    }

#pragma unroll
    for (int m = 0; m < TM; m++) {
        int row = brow + ty + m;
#pragma unroll
        for (int n = 0; n < TN; n++) {
            int col = bcol + tx + n;
            float v = acc[m][n] + 2.f * bias[col];
            out[(size_t)row * UNITS + col] = fmaxf(v, 0.f);
        }
    }
}

// ---------------------------------------------------------------------------
// Launch. Input order per setup_inputs():
// 0: inputs [4096,4096]  1: context [4096,512]  2: U [4096,256]  3: S [256]
// 4: V [4096,256]        5: W [512,256]         6: B [256]       7: bias [4096]
// ---------------------------------------------------------------------------
extern "C" void kernel_launch(void* const* d_in, const int* in_sizes, int n_in,
                              void* d_out, int out_size)
{
    const float* inputs  = (const float*)d_in[0];
    const float* context = (const float*)d_in[1];
    const float* U       = (const float*)d_in[2];
    const float* S       = (const float*)d_in[3];
    const float* V       = (const float*)d_in[4];
    const float* W       = (const float*)d_in[5];
    const float* Bvec    = (const float*)d_in[6];
    const float* bias    = (const float*)d_in[7];
    float* out = (float*)d_out;

    dim3 blk(NTHREADS);
    // chi: M=4096, N=256
    k_chi<<<dim3(RANK / BN, B_SZ / BM), blk>>>(context, W, S, Bvec);
    // t: M=4096, N=256, K=4096
    k_t<<<dim3(RANK / BN, B_SZ / BM), blk>>>(inputs, U);
    // out: M=4096, N=4096, K=256
    k_out<<<dim3(UNITS / BN, B_SZ / BM), blk>>>(out, V, bias);
}

// round 4
// speedup vs baseline: 2.6295x; 2.6295x over previous
#include <cuda_runtime.h>
#include <cuda_bf16.h>
#include <cstdint>
#include <math.h>

// Problem dims (fixed)
#define B_SZ   4096
#define N_IN   4096
#define N_CTX  512
#define UNITS  4096
#define RANK   256

// ---------------------------------------------------------------------------
// Device scratch (no allocation allowed). Align for vector loads.
// ---------------------------------------------------------------------------
__device__ __align__(16) unsigned short g_t_hi[B_SZ * RANK];
__device__ __align__(16) unsigned short g_t_lo[B_SZ * RANK];
__device__ __align__(16) unsigned short g_Ut_hi[RANK * N_IN];   // U^T [256][4096]
__device__ __align__(16) unsigned short g_Ut_lo[RANK * N_IN];
__device__ __align__(16) unsigned short g_V_hi[UNITS * RANK];   // V [4096][256]
__device__ __align__(16) unsigned short g_V_lo[UNITS * RANK];
__device__ __align__(16) unsigned short g_Wt_hi[RANK * N_CTX];  // W^T [256][512]
__device__ __align__(16) unsigned short g_Wt_lo[RANK * N_CTX];
__device__ __align__(16) float          g_schi[B_SZ * RANK];

// ---------------------------------------------------------------------------
// Helpers
// ---------------------------------------------------------------------------
__device__ __forceinline__ uint32_t smem_to_u32(const void* p) {
    uint32_t a;
    asm("{ .reg .u64 t; cvta.to.shared.u64 t, %1; cvt.u32.u64 %0, t; }"
        : "=r"(a) : "l"(p));
    return a;
}

__device__ __forceinline__ void ldmx4(uint32_t* r, uint32_t addr) {
    asm volatile("ldmatrix.sync.aligned.m8n8.x4.shared.b16 {%0,%1,%2,%3}, [%4];\n"
                 : "=r"(r[0]), "=r"(r[1]), "=r"(r[2]), "=r"(r[3]) : "r"(addr));
}

__device__ __forceinline__ void mma_bf16(float* c, const uint32_t* a, const uint32_t* b) {
    asm volatile(
        "mma.sync.aligned.m16n8k16.row.col.f32.bf16.bf16.f32 "
        "{%0,%1,%2,%3}, {%4,%5,%6,%7}, {%8,%9}, {%0,%1,%2,%3};\n"
        : "+f"(c[0]), "+f"(c[1]), "+f"(c[2]), "+f"(c[3])
        : "r"(a[0]), "r"(a[1]), "r"(a[2]), "r"(a[3]), "r"(b[0]), "r"(b[1]));
}

#define CP_ASYNC16(saddr, gptr) \
    asm volatile("cp.async.cg.shared.global [%0], [%1], 16;\n" \
                 :: "r"(saddr), "l"(gptr))
#define CP_COMMIT() asm volatile("cp.async.commit_group;\n" ::: "memory")
#define CP_WAIT0()  asm volatile("cp.async.wait_group 0;\n" ::: "memory")

__device__ __forceinline__ void split2(float x, unsigned short& h, unsigned short& l) {
    __nv_bfloat16 hb = __float2bfloat16_rn(x);
    h = *reinterpret_cast<unsigned short*>(&hb);
    float r = x - __bfloat162float(hb);
    __nv_bfloat16 lb = __float2bfloat16_rn(r);
    l = *reinterpret_cast<unsigned short*>(&lb);
}

// ---------------------------------------------------------------------------
// Conversion kernels
// ---------------------------------------------------------------------------
// V [4096,256] fp32 -> hi/lo bf16, same layout (already [N][K] K-major)
__global__ __launch_bounds__(256)
void k_conv_V(const float* __restrict__ V)
{
    size_t i = ((size_t)blockIdx.x * 256 + threadIdx.x) * 4;
    float4 v = *(const float4*)(V + i);
    ushort4 h, l;
    split2(v.x, h.x, l.x);
    split2(v.y, h.y, l.y);
    split2(v.z, h.z, l.z);
    split2(v.w, h.w, l.w);
    *(ushort4*)(g_V_hi + i) = h;
    *(ushort4*)(g_V_lo + i) = l;
}

// Transpose + split: src [R][C] fp32 -> dst [C][R] hi/lo bf16.
// DST=0 -> g_Ut (R=4096,C=256);  DST=1 -> g_Wt (R=512,C=256)
template <int DST>
__global__ __launch_bounds__(256)
void k_conv_T(const float* __restrict__ src, int R, int C)
{
    __shared__ float tile[32][33];
    int c0 = blockIdx.x * 32;
    int r0 = blockIdx.y * 32;
    int tx = threadIdx.x, ty = threadIdx.y;
    for (int i = ty; i < 32; i += 8)
        tile[i][tx] = src[(size_t)(r0 + i) * C + c0 + tx];
    __syncthreads();
    unsigned short* dhi = (DST == 0) ? g_Ut_hi : g_Wt_hi;
    unsigned short* dlo = (DST == 0) ? g_Ut_lo : g_Wt_lo;
    for (int i = ty; i < 32; i += 8) {
        int c = c0 + i, r = r0 + tx;
        float x = tile[tx][i];
        unsigned short h, l;
        split2(x, h, l);
        dhi[(size_t)c * R + r] = h;
        dlo[(size_t)c * R + r] = l;
    }
}

// ---------------------------------------------------------------------------
// Generic split-bf16 mma.sync GEMM.
//   C[128 x TILEN] tile per CTA over K = KTOT.
//   A: EPI 0/1 -> fp32 global [M][KTOT] (converted on the fly)
//      EPI 2   -> pre-split bf16 (g_t_hi / g_t_lo), [M][KTOT]
//   B: pre-split bf16 [N][KTOT] (K-major): EPI0 g_Wt, EPI1 g_Ut, EPI2 g_V
//   EPI 0: g_schi = S * sigmoid(acc + Bvec)
//   EPI 1: t = acc * g_schi -> g_t_hi/lo
//   EPI 2: out = relu(acc + 2*bias)
// ---------------------------------------------------------------------------
template <int TILEN, int WARPS_N, int KTOT, int EPI>
__global__ __launch_bounds__(256)
void mma_gemm(const float* __restrict__ Afp,
              float* __restrict__ outp,
              const float* __restrict__ ev0,   // EPI0: S, EPI2: bias
              const float* __restrict__ ev1)   // EPI0: Bvec
{
    constexpr int WARPS_M = 8 / WARPS_N;
    constexpr int WM = 128 / WARPS_M;      // 32 or 64
    constexpr int MI = WM / 16;            // 2 or 4
    constexpr int NI = 4;                  // WN = 32 fixed
    constexpr int ASZ = 128 * 40 * 2;      // bytes per A half-buffer (pad 40 halves)
    constexpr int BSZ = TILEN * 40 * 2;
    constexpr int STG = 2 * ASZ + 2 * BSZ;
    constexpr int NC  = KTOT / 32;
    constexpr int NBIT = TILEN / 64;       // B cp iters per half (1 or 2)
    static_assert(WARPS_N * 32 == TILEN, "tile mismatch");

    extern __shared__ char smem[];
    const uint32_t sb = smem_to_u32(smem);

    const int tid = threadIdx.x;
    const int wid = tid >> 5, lid = tid & 31;
    const int wm = wid / WARPS_N, wn = wid % WARPS_N;
    const int warp_row = wm * WM;
    const int warp_col = wn * 32;
    const int brow = blockIdx.y * 128;
    const int bn0  = blockIdx.x * TILEN;

    const unsigned short* Bhig = (EPI == 0) ? g_Wt_hi : (EPI == 1) ? g_Ut_hi : g_V_hi;
    const unsigned short* Blog = (EPI == 0) ? g_Wt_lo : (EPI == 1) ? g_Ut_lo : g_V_lo;

    float acc[MI][NI][4];
#pragma unroll
    for (int mi = 0; mi < MI; mi++)
#pragma unroll
        for (int ni = 0; ni < NI; ni++)
#pragma unroll
            for (int q = 0; q < 4; q++) acc[mi][ni][q] = 0.f;

    // ldmatrix per-lane byte offsets within a tile buffer
    const uint32_t a_lane = (uint32_t)(((lid & 15) * 40 + (lid >> 4) * 8) * 2);
    const uint32_t b_lane = (uint32_t)((((lid & 7) + ((lid >> 4) << 3)) * 40 +
                                        ((lid >> 3) & 1) * 8) * 2);

    // ---------------- prologue: chunk 0 into stage 0 (synchronous) ----------
    {
        const uint32_t Ah = sb, Al = sb + ASZ, Bh = sb + 2 * ASZ, Bl = Bh + BSZ;
        if (EPI < 2) {
#pragma unroll
            for (int it = 0; it < 4; it++) {
                int flat = it * 256 + tid;
                int row = flat >> 3, j = (flat & 7) << 2;
                float4 a = *(const float4*)(Afp + (size_t)(brow + row) * KTOT + j);
                ushort4 h, l;
                split2(a.x, h.x, l.x); split2(a.y, h.y, l.y);
                split2(a.z, h.z, l.z); split2(a.w, h.w, l.w);
                uint32_t off = (uint32_t)((row * 40 + j) * 2);
                *(ushort4*)(smem + (Ah - sb) + off) = h;
                *(ushort4*)(smem + (Al - sb) + off) = l;
            }
        } else {
#pragma unroll
            for (int it = 0; it < 2; it++) {
                int flat = it * 256 + tid;
                int row = flat >> 2, j = (flat & 3) << 3;
                uint4 h = *(const uint4*)(g_t_hi + (size_t)(brow + row) * KTOT + j);
                uint4 l = *(const uint4*)(g_t_lo + (size_t)(brow + row) * KTOT + j);
                uint32_t off = (uint32_t)((row * 40 + j) * 2);
                *(uint4*)(smem + (Ah - sb) + off) = h;
                *(uint4*)(smem + (Al - sb) + off) = l;
            }
        }
#pragma unroll
        for (int it = 0; it < NBIT; it++) {
            int flat = it * 256 + tid;
            int row = flat >> 2, j = (flat & 3) << 3;
            uint4 h = *(const uint4*)(Bhig + (size_t)(bn0 + row) * KTOT + j);
            uint4 l = *(const uint4*)(Blog + (size_t)(bn0 + row) * KTOT + j);
            uint32_t off = (uint32_t)((row * 40 + j) * 2);
            *(uint4*)(smem + (Bh - sb) + off) = h;
            *(uint4*)(smem + (Bl - sb) + off) = l;
        }
    }
    __syncthreads();

    // ---------------- main loop ----------------
    int cur = 0;
    for (int ch = 0; ch < NC; ch++) {
        const bool has = (ch + 1 < NC);
        const int k0n = (ch + 1) * 32;
        float4 pf[4];

        if (has) {
            const uint32_t nb = sb + (cur ^ 1) * STG;
            const uint32_t Ahn = nb, Aln = nb + ASZ, Bhn = nb + 2 * ASZ, Bln = Bhn + BSZ;
            if (EPI < 2) {
#pragma unroll
                for (int it = 0; it < 4; it++) {
                    int flat = it * 256 + tid;
                    int row = flat >> 3, j = (flat & 7) << 2;
                    pf[it] = *(const float4*)(Afp + (size_t)(brow + row) * KTOT + k0n + j);
                }
            } else {
#pragma unroll
                for (int it = 0; it < 2; it++) {
                    int flat = it * 256 + tid;
                    int row = flat >> 2, j = (flat & 3) << 3;
                    uint32_t off = (uint32_t)((row * 40 + j) * 2);
                    CP_ASYNC16(Ahn + off, g_t_hi + (size_t)(brow + row) * KTOT + k0n + j);
                    CP_ASYNC16(Aln + off, g_t_lo + (size_t)(brow + row) * KTOT + k0n + j);
                }
            }
#pragma unroll
            for (int it = 0; it < NBIT; it++) {
                int flat = it * 256 + tid;
                int row = flat >> 2, j = (flat & 3) << 3;
                uint32_t off = (uint32_t)((row * 40 + j) * 2);
                CP_ASYNC16(Bhn + off, Bhig + (size_t)(bn0 + row) * KTOT + k0n + j);
                CP_ASYNC16(Bln + off, Blog + (size_t)(bn0 + row) * KTOT + k0n + j);
            }
            CP_COMMIT();
        }

        // compute on stage cur
        {
            const uint32_t cb = sb + cur * STG;
            const uint32_t Ah = cb, Al = cb + ASZ, Bh = cb + 2 * ASZ, Bl = Bh + BSZ;
#pragma unroll
            for (int ks = 0; ks < 2; ks++) {
                uint32_t afh[MI][4], afl[MI][4], bfh[2][4], bfl[2][4];
#pragma unroll
                for (int mi = 0; mi < MI; mi++) {
                    uint32_t ao = a_lane + (uint32_t)((warp_row + mi * 16) * 80 + ks * 32);
                    ldmx4(afh[mi], Ah + ao);
                    ldmx4(afl[mi], Al + ao);
                }
#pragma unroll
                for (int j = 0; j < 2; j++) {
                    uint32_t bo = b_lane + (uint32_t)((warp_col + j * 16) * 80 + ks * 32);
                    ldmx4(bfh[j], Bh + bo);
                    ldmx4(bfl[j], Bl + bo);
                }
#pragma unroll
                for (int mi = 0; mi < MI; mi++) {
#pragma unroll
                    for (int ni = 0; ni < NI; ni++) {
                        const uint32_t* bh = &bfh[ni >> 1][(ni & 1) * 2];
                        const uint32_t* bl = &bfl[ni >> 1][(ni & 1) * 2];
                        mma_bf16(acc[mi][ni], afh[mi], bh);
                        mma_bf16(acc[mi][ni], afh[mi], bl);
                        mma_bf16(acc[mi][ni], afl[mi], bh);
                    }
                }
            }
        }

        if (has) {
            if (EPI < 2) {
                const uint32_t nb = sb + (cur ^ 1) * STG;
#pragma unroll
                for (int it = 0; it < 4; it++) {
                    int flat = it * 256 + tid;
                    int row = flat >> 3, j = (flat & 7) << 2;
                    ushort4 h, l;
                    split2(pf[it].x, h.x, l.x);
                    split2(pf[it].y, h.y, l.y);
                    split2(pf[it].z, h.z, l.z);
                    split2(pf[it].w, h.w, l.w);
                    uint32_t off = (uint32_t)((row * 40 + j) * 2);
                    *(ushort4*)(smem + (nb - sb) + off) = h;
                    *(ushort4*)(smem + (nb - sb) + ASZ + off) = l;
                }
            }
            CP_WAIT0();
        }
        __syncthreads();
        cur ^= 1;
    }

    // ---------------- epilogue ----------------
    const int g = lid >> 2, t = lid & 3;
#pragma unroll
    for (int mi = 0; mi < MI; mi++) {
#pragma unroll
        for (int ni = 0; ni < NI; ni++) {
            int row0 = brow + warp_row + mi * 16 + g;
            int row1 = row0 + 8;
            int col  = bn0 + warp_col + ni * 8 + 2 * t;
            const float* a = acc[mi][ni];
            if (EPI == 0) {
                float bv0 = ev1[col], bv1 = ev1[col + 1];
                float s0 = ev0[col], s1 = ev0[col + 1];
                float x00 = a[0] + bv0, x01 = a[1] + bv1;
                float x10 = a[2] + bv0, x11 = a[3] + bv1;
                float2 r0 = make_float2(s0 / (1.f + expf(-x00)), s1 / (1.f + expf(-x01)));
                float2 r1 = make_float2(s0 / (1.f + expf(-x10)), s1 / (1.f + expf(-x11)));
                *(float2*)(g_schi + (size_t)row0 * RANK + col) = r0;
                *(float2*)(g_schi + (size_t)row1 * RANK + col) = r1;
            } else if (EPI == 1) {
                size_t i0 = (size_t)row0 * RANK + col;
                size_t i1 = (size_t)row1 * RANK + col;
                float t00 = a[0] * g_schi[i0], t01 = a[1] * g_schi[i0 + 1];
                float t10 = a[2] * g_schi[i1], t11 = a[3] * g_schi[i1 + 1];
                ushort2 h0, l0, h1, l1;
                split2(t00, h0.x, l0.x); split2(t01, h0.y, l0.y);
                split2(t10, h1.x, l1.x); split2(t11, h1.y, l1.y);
                *(ushort2*)(g_t_hi + i0) = h0; *(ushort2*)(g_t_lo + i0) = l0;
                *(ushort2*)(g_t_hi + i1) = h1; *(ushort2*)(g_t_lo + i1) = l1;
            } else {
                float b0 = 2.f * ev0[col], b1 = 2.f * ev0[col + 1];
                float2 r0 = make_float2(fmaxf(a[0] + b0, 0.f), fmaxf(a[1] + b1, 0.f));
                float2 r1 = make_float2(fmaxf(a[2] + b0, 0.f), fmaxf(a[3] + b1, 0.f));
                *(float2*)(outp + (size_t)row0 * UNITS + col) = r0;
                *(float2*)(outp + (size_t)row1 * UNITS + col) = r1;
            }
        }
    }
}

// ---------------------------------------------------------------------------
// Launch. Input order:
// 0: inputs [4096,4096]  1: context [4096,512]  2: U [4096,256]  3: S [256]
// 4: V [4096,256]        5: W [512,256]         6: B [256]       7: bias [4096]
// ---------------------------------------------------------------------------
extern "C" void kernel_launch(void* const* d_in, const int* in_sizes, int n_in,
                              void* d_out, int out_size)
{
    const float* inputs  = (const float*)d_in[0];
    const float* context = (const float*)d_in[1];
    const float* U       = (const float*)d_in[2];
    const float* S       = (const float*)d_in[3];
    const float* V       = (const float*)d_in[4];
    const float* W       = (const float*)d_in[5];
    const float* Bvec    = (const float*)d_in[6];
    const float* bias    = (const float*)d_in[7];
    float* out = (float*)d_out;

    // dynamic smem sizes: STG*2
    const int smem_small = 2 * (2 * 128 * 80 + 2 * 64 * 80);    // 61440
    const int smem_big   = 2 * (2 * 128 * 80 + 2 * 128 * 80);   // 81920

    cudaFuncSetAttribute(mma_gemm<64, 2, 512, 0>,
                         cudaFuncAttributeMaxDynamicSharedMemorySize, smem_small);
    cudaFuncSetAttribute(mma_gemm<64, 2, 4096, 1>,
                         cudaFuncAttributeMaxDynamicSharedMemorySize, smem_small);
    cudaFuncSetAttribute(mma_gemm<128, 4, 256, 2>,
                         cudaFuncAttributeMaxDynamicSharedMemorySize, smem_big);

    // conversions
    k_conv_T<0><<<dim3(RANK / 32, N_IN / 32), dim3(32, 8)>>>(U, N_IN, RANK);
    k_conv_T<1><<<dim3(RANK / 32, N_CTX / 32), dim3(32, 8)>>>(W, N_CTX, RANK);
    k_conv_V<<<(UNITS * RANK) / (256 * 4), 256>>>(V);

    // chi: schi = S*sigmoid(context @ W^T' + B)   [4096 x 256], K=512
    mma_gemm<64, 2, 512, 0><<<dim3(RANK / 64, B_SZ / 128), 256, smem_small>>>(
        context, nullptr, S, Bvec);
    // t = (inputs @ U) * schi  [4096 x 256], K=4096
    mma_gemm<64, 2, 4096, 1><<<dim3(RANK / 64, B_SZ / 128), 256, smem_small>>>(
        inputs, nullptr, nullptr, nullptr);
    // out = relu(t @ V^T + 2*bias)  [4096 x 4096], K=256
    mma_gemm<128, 4, 256, 2><<<dim3(UNITS / 128, B_SZ / 128), 256, smem_big>>>(
        nullptr, out, bias, nullptr);
}

// round 6
// speedup vs baseline: 2.8300x; 1.0763x over previous
#include <cuda_runtime.h>
#include <cuda_bf16.h>
#include <cstdint>
#include <math.h>

// Problem dims (fixed)
#define B_SZ   4096
#define N_IN   4096
#define N_CTX  512
#define UNITS  4096
#define RANK   256

// ---------------------------------------------------------------------------
// Device scratch (bf16 hi/lo split operands)
// ---------------------------------------------------------------------------
__device__ __align__(16) unsigned short g_in_hi[B_SZ * N_IN];   // inputs
__device__ __align__(16) unsigned short g_in_lo[B_SZ * N_IN];
__device__ __align__(16) unsigned short g_ctx_hi[B_SZ * N_CTX]; // context
__device__ __align__(16) unsigned short g_ctx_lo[B_SZ * N_CTX];
__device__ __align__(16) unsigned short g_t_hi[B_SZ * RANK];
__device__ __align__(16) unsigned short g_t_lo[B_SZ * RANK];
__device__ __align__(16) unsigned short g_Ut_hi[RANK * N_IN];   // U^T [256][4096]
__device__ __align__(16) unsigned short g_Ut_lo[RANK * N_IN];
__device__ __align__(16) unsigned short g_V_hi[UNITS * RANK];   // V [4096][256]
__device__ __align__(16) unsigned short g_V_lo[UNITS * RANK];
__device__ __align__(16) unsigned short g_Wt_hi[RANK * N_CTX];  // W^T [256][512]
__device__ __align__(16) unsigned short g_Wt_lo[RANK * N_CTX];
__device__ __align__(16) float          g_schi[B_SZ * RANK];

// ---------------------------------------------------------------------------
// Helpers
// ---------------------------------------------------------------------------
__device__ __forceinline__ uint32_t smem_to_u32(const void* p) {
    uint32_t a;
    asm("{ .reg .u64 t; cvta.to.shared.u64 t, %1; cvt.u32.u64 %0, t; }"
        : "=r"(a) : "l"(p));
    return a;
}

__device__ __forceinline__ void ldmx4(uint32_t* r, uint32_t addr) {
    asm volatile("ldmatrix.sync.aligned.m8n8.x4.shared.b16 {%0,%1,%2,%3}, [%4];\n"
                 : "=r"(r[0]), "=r"(r[1]), "=r"(r[2]), "=r"(r[3]) : "r"(addr));
}

__device__ __forceinline__ void mma_bf16(float* c, const uint32_t* a, const uint32_t* b) {
    asm volatile(
        "mma.sync.aligned.m16n8k16.row.col.f32.bf16.bf16.f32 "
        "{%0,%1,%2,%3}, {%4,%5,%6,%7}, {%8,%9}, {%0,%1,%2,%3};\n"
        : "+f"(c[0]), "+f"(c[1]), "+f"(c[2]), "+f"(c[3])
        : "r"(a[0]), "r"(a[1]), "r"(a[2]), "r"(a[3]), "r"(b[0]), "r"(b[1]));
}

#define CP_ASYNC16(saddr, gptr) \
    asm volatile("cp.async.cg.shared.global [%0], [%1], 16;\n" \
                 :: "r"(saddr), "l"(gptr))
#define CP_COMMIT() asm volatile("cp.async.commit_group;\n" ::: "memory")

template <int N>
__device__ __forceinline__ void cp_wait_group() {
    asm volatile("cp.async.wait_group %0;\n" :: "n"(N) : "memory");
}

__device__ __forceinline__ void split2(float x, unsigned short& h, unsigned short& l) {
    __nv_bfloat16 hb = __float2bfloat16_rn(x);
    h = *reinterpret_cast<unsigned short*>(&hb);
    float r = x - __bfloat162float(hb);
    __nv_bfloat16 lb = __float2bfloat16_rn(r);
    l = *reinterpret_cast<unsigned short*>(&lb);
}

// ---------------------------------------------------------------------------
// Conversion kernels — destinations selected in DEVICE code (device globals
// cannot be passed as kernel args from host).
// ---------------------------------------------------------------------------
// Elementwise split, layout preserved. DST: 0=inputs, 1=context, 2=V
template <int DST>
__global__ __launch_bounds__(256)
void k_split(const float* __restrict__ src)
{
    unsigned short* dhi = (DST == 0) ? g_in_hi : (DST == 1) ? g_ctx_hi : g_V_hi;
    unsigned short* dlo = (DST == 0) ? g_in_lo : (DST == 1) ? g_ctx_lo : g_V_lo;
    size_t i = ((size_t)blockIdx.x * 256 + threadIdx.x) * 4;
    float4 v = *(const float4*)(src + i);
    ushort4 h, l;
    split2(v.x, h.x, l.x);
    split2(v.y, h.y, l.y);
    split2(v.z, h.z, l.z);
    split2(v.w, h.w, l.w);
    *(ushort4*)(dhi + i) = h;
    *(ushort4*)(dlo + i) = l;
}

// Transpose + split: src [R][C] fp32 -> dst [C][R] hi/lo bf16.
// DST=0 -> g_Ut (R=4096), DST=1 -> g_Wt (R=512)
template <int DST>
__global__ __launch_bounds__(256)
void k_conv_T(const float* __restrict__ src, int R, int C)
{
    __shared__ float tile[32][33];
    int c0 = blockIdx.x * 32;
    int r0 = blockIdx.y * 32;
    int tx = threadIdx.x, ty = threadIdx.y;
    for (int i = ty; i < 32; i += 8)
        tile[i][tx] = src[(size_t)(r0 + i) * C + c0 + tx];
    __syncthreads();
    unsigned short* dhi = (DST == 0) ? g_Ut_hi : g_Wt_hi;
    unsigned short* dlo = (DST == 0) ? g_Ut_lo : g_Wt_lo;
    for (int i = ty; i < 32; i += 8) {
        int c = c0 + i, r = r0 + tx;
        float x = tile[tx][i];
        unsigned short h, l;
        split2(x, h, l);
        dhi[(size_t)c * R + r] = h;
        dlo[(size_t)c * R + r] = l;
    }
}

// ---------------------------------------------------------------------------
// Unified split-bf16 mma.sync GEMM, STAGES-deep cp.async pipeline.
//   C[128 x TILEN] per CTA over K = KTOT (chunks of 32).
//   A (bf16 hi/lo, [M][KTOT]): EPI0 g_ctx, EPI1 g_in, EPI2 g_t
//   B (bf16 hi/lo, [N][KTOT]): EPI0 g_Wt,  EPI1 g_Ut, EPI2 g_V
//   EPI 0: g_schi = S * sigmoid(acc + Bvec)
//   EPI 1: t = acc * g_schi -> g_t hi/lo
//   EPI 2: out = relu(acc + 2*bias)
// ---------------------------------------------------------------------------
template <int TILEN, int WARPS_N, int KTOT, int EPI, int STAGES>
__global__ __launch_bounds__(256)
void mma_gemm(float* __restrict__ outp,
              const float* __restrict__ ev0,   // EPI0: S, EPI2: bias
              const float* __restrict__ ev1)   // EPI0: Bvec
{
    constexpr int WARPS_M = 8 / WARPS_N;
    constexpr int WM = 128 / WARPS_M;        // 32 or 64
    constexpr int MI = WM / 16;              // 2 or 4
    constexpr int NI = 4;                    // WN = 32 fixed
    constexpr int AHB = 128 * 40 * 2;        // bytes per A half-stage (pitch 40 halves)
    constexpr int BHB = TILEN * 40 * 2;
    constexpr int STG = 2 * AHB + 2 * BHB;
    constexpr int NC  = KTOT / 32;
    constexpr int B_IT = TILEN * 4 / 256;    // B cp iters per half (1 or 2)
    static_assert(WARPS_N * 32 == TILEN, "tile mismatch");

    extern __shared__ char smem[];
    const uint32_t sb = smem_to_u32(smem);

    const int tid = threadIdx.x;
    const int wid = tid >> 5, lid = tid & 31;
    const int wm = wid / WARPS_N, wn = wid % WARPS_N;
    const int warp_row = wm * WM;
    const int warp_col = wn * 32;
    const int brow = blockIdx.y * 128;
    const int bn0  = blockIdx.x * TILEN;

    const unsigned short* Ahg = (EPI == 0) ? g_ctx_hi : (EPI == 1) ? g_in_hi : g_t_hi;
    const unsigned short* Alg = (EPI == 0) ? g_ctx_lo : (EPI == 1) ? g_in_lo : g_t_lo;
    const unsigned short* Bhg = (EPI == 0) ? g_Wt_hi : (EPI == 1) ? g_Ut_hi : g_V_hi;
    const unsigned short* Blg = (EPI == 0) ? g_Wt_lo : (EPI == 1) ? g_Ut_lo : g_V_lo;

    float acc[MI][NI][4];
#pragma unroll
    for (int mi = 0; mi < MI; mi++)
#pragma unroll
        for (int ni = 0; ni < NI; ni++)
#pragma unroll
            for (int q = 0; q < 4; q++) acc[mi][ni][q] = 0.f;

    // ldmatrix per-lane byte offsets (pitch = 40 halves = 80 B)
    const uint32_t a_lane = (uint32_t)(((lid & 15) * 40 + (lid >> 4) * 8) * 2);
    const uint32_t b_lane = (uint32_t)((((lid & 7) + ((lid >> 4) << 3)) * 40 +
                                        ((lid >> 3) & 1) * 8) * 2);

    // stage loader: issues cp.asyncs for chunk k0 into stage slot s
    auto load_stage = [&](int s, int k0) {
        const uint32_t st = sb + (uint32_t)(s * STG);
#pragma unroll
        for (int it = 0; it < 2; it++) {          // A: 128 rows x 4 segs = 512 tasks
            int flat = it * 256 + tid;
            int row = flat >> 2, seg = flat & 3;
            uint32_t off = (uint32_t)(row * 80 + seg * 16);
            size_t gi = (size_t)(brow + row) * KTOT + k0 + seg * 8;
            CP_ASYNC16(st + off, Ahg + gi);
            CP_ASYNC16(st + AHB + off, Alg + gi);
        }
#pragma unroll
        for (int it = 0; it < B_IT; it++) {       // B: TILEN rows x 4 segs
            int flat = it * 256 + tid;
            int row = flat >> 2, seg = flat & 3;
            uint32_t off = (uint32_t)(row * 80 + seg * 16);
            size_t gi = (size_t)(bn0 + row) * KTOT + k0 + seg * 8;
            CP_ASYNC16(st + 2 * AHB + off, Bhg + gi);
            CP_ASYNC16(st + 2 * AHB + BHB + off, Blg + gi);
        }
    };

    // prologue: fill STAGES-1 stages
#pragma unroll
    for (int s = 0; s < STAGES - 1; s++) {
        load_stage(s, s * 32);
        CP_COMMIT();
    }

    // main loop
    for (int ch = 0; ch < NC; ch++) {
        cp_wait_group<STAGES - 2>();
        __syncthreads();

        const uint32_t cb = sb + (uint32_t)((ch % STAGES) * STG);
        const uint32_t Ah = cb, Al = cb + AHB, Bh = cb + 2 * AHB, Bl = Bh + BHB;
#pragma unroll
        for (int ks = 0; ks < 2; ks++) {
            uint32_t afh[MI][4], afl[MI][4], bfh[2][4], bfl[2][4];
#pragma unroll
            for (int mi = 0; mi < MI; mi++) {
                uint32_t ao = a_lane + (uint32_t)((warp_row + mi * 16) * 80 + ks * 32);
                ldmx4(afh[mi], Ah + ao);
                ldmx4(afl[mi], Al + ao);
            }
#pragma unroll
            for (int j = 0; j < 2; j++) {
                uint32_t bo = b_lane + (uint32_t)((warp_col + j * 16) * 80 + ks * 32);
                ldmx4(bfh[j], Bh + bo);
                ldmx4(bfl[j], Bl + bo);
            }
#pragma unroll
            for (int mi = 0; mi < MI; mi++) {
#pragma unroll
                for (int ni = 0; ni < NI; ni++) {
                    const uint32_t* bh = &bfh[ni >> 1][(ni & 1) * 2];
                    const uint32_t* bl = &bfl[ni >> 1][(ni & 1) * 2];
                    mma_bf16(acc[mi][ni], afh[mi], bh);
                    mma_bf16(acc[mi][ni], afh[mi], bl);
                    mma_bf16(acc[mi][ni], afl[mi], bh);
                }
            }
        }

        // issue next stage (or empty group to keep wait bookkeeping uniform)
        if (ch + STAGES - 1 < NC)
            load_stage((ch + STAGES - 1) % STAGES, (ch + STAGES - 1) * 32);
        CP_COMMIT();
    }

    // ---------------- epilogue ----------------
    const int g = lid >> 2, t = lid & 3;
#pragma unroll
    for (int mi = 0; mi < MI; mi++) {
#pragma unroll
        for (int ni = 0; ni < NI; ni++) {
            int row0 = brow + warp_row + mi * 16 + g;
            int row1 = row0 + 8;
            int col  = bn0 + warp_col + ni * 8 + 2 * t;
            const float* a = acc[mi][ni];
            if (EPI == 0) {
                float bv0 = ev1[col], bv1 = ev1[col + 1];
                float s0 = ev0[col], s1 = ev0[col + 1];
                float x00 = a[0] + bv0, x01 = a[1] + bv1;
                float x10 = a[2] + bv0, x11 = a[3] + bv1;
                float2 r0 = make_float2(s0 / (1.f + expf(-x00)), s1 / (1.f + expf(-x01)));
                float2 r1 = make_float2(s0 / (1.f + expf(-x10)), s1 / (1.f + expf(-x11)));
                *(float2*)(g_schi + (size_t)row0 * RANK + col) = r0;
                *(float2*)(g_schi + (size_t)row1 * RANK + col) = r1;
            } else if (EPI == 1) {
                size_t i0 = (size_t)row0 * RANK + col;
                size_t i1 = (size_t)row1 * RANK + col;
                float t00 = a[0] * g_schi[i0], t01 = a[1] * g_schi[i0 + 1];
                float t10 = a[2] * g_schi[i1], t11 = a[3] * g_schi[i1 + 1];
                ushort2 h0, l0, h1, l1;
                split2(t00, h0.x, l0.x); split2(t01, h0.y, l0.y);
                split2(t10, h1.x, l1.x); split2(t11, h1.y, l1.y);
                *(ushort2*)(g_t_hi + i0) = h0; *(ushort2*)(g_t_lo + i0) = l0;
                *(ushort2*)(g_t_hi + i1) = h1; *(ushort2*)(g_t_lo + i1) = l1;
            } else {
                float b0 = 2.f * ev0[col], b1 = 2.f * ev0[col + 1];
                float2 r0 = make_float2(fmaxf(a[0] + b0, 0.f), fmaxf(a[1] + b1, 0.f));
                float2 r1 = make_float2(fmaxf(a[2] + b0, 0.f), fmaxf(a[3] + b1, 0.f));
                *(float2*)(outp + (size_t)row0 * UNITS + col) = r0;
                *(float2*)(outp + (size_t)row1 * UNITS + col) = r1;
            }
        }
    }
}

// ---------------------------------------------------------------------------
// Launch. Input order:
// 0: inputs [4096,4096]  1: context [4096,512]  2: U [4096,256]  3: S [256]
// 4: V [4096,256]        5: W [512,256]         6: B [256]       7: bias [4096]
// ---------------------------------------------------------------------------
extern "C" void kernel_launch(void* const* d_in, const int* in_sizes, int n_in,
                              void* d_out, int out_size)
{
    const float* inputs  = (const float*)d_in[0];
    const float* context = (const float*)d_in[1];
    const float* U       = (const float*)d_in[2];
    const float* S       = (const float*)d_in[3];
    const float* V       = (const float*)d_in[4];
    const float* W       = (const float*)d_in[5];
    const float* Bvec    = (const float*)d_in[6];
    const float* bias    = (const float*)d_in[7];
    float* out = (float*)d_out;

    constexpr int STG64  = 2 * (128 * 80) + 2 * (64 * 80);   // 30720
    constexpr int STG128 = 2 * (128 * 80) + 2 * (128 * 80);  // 40960
    const int smem_chi   = 4 * STG64;    // 122880
    const int smem_g1    = 4 * STG64;    // 122880
    const int smem_g2    = 4 * STG128;   // 163840

    cudaFuncSetAttribute(mma_gemm<64, 2, 512, 0, 4>,
                         cudaFuncAttributeMaxDynamicSharedMemorySize, smem_chi);
    cudaFuncSetAttribute(mma_gemm<64, 2, 4096, 1, 4>,
                         cudaFuncAttributeMaxDynamicSharedMemorySize, smem_g1);
    cudaFuncSetAttribute(mma_gemm<128, 4, 256, 2, 4>,
                         cudaFuncAttributeMaxDynamicSharedMemorySize, smem_g2);

    // conversions (bf16 hi/lo splits)
    k_split<0><<<(size_t)B_SZ * N_IN / 1024, 256>>>(inputs);
    k_split<1><<<(size_t)B_SZ * N_CTX / 1024, 256>>>(context);
    k_split<2><<<(size_t)UNITS * RANK / 1024, 256>>>(V);
    k_conv_T<0><<<dim3(RANK / 32, N_IN / 32), dim3(32, 8)>>>(U, N_IN, RANK);
    k_conv_T<1><<<dim3(RANK / 32, N_CTX / 32), dim3(32, 8)>>>(W, N_CTX, RANK);

    // chi: schi = S*sigmoid(context @ W^T + B)   [4096 x 256], K=512
    mma_gemm<64, 2, 512, 0, 4><<<dim3(RANK / 64, B_SZ / 128), 256, smem_chi>>>(
        nullptr, S, Bvec);
    // t = (inputs @ U) * schi  [4096 x 256], K=4096
    mma_gemm<64, 2, 4096, 1, 4><<<dim3(RANK / 64, B_SZ / 128), 256, smem_g1>>>(
        nullptr, nullptr, nullptr);
    // out = relu(t @ V^T + 2*bias)  [4096 x 4096], K=256
    mma_gemm<128, 4, 256, 2, 4><<<dim3(UNITS / 128, B_SZ / 128), 256, smem_g2>>>(
        out, bias, nullptr);
}